// round 7
// baseline (speedup 1.0000x reference)
#include <cuda_runtime.h>
#include <cuda_fp16.h>
#include <cstdint>

// ---------------- problem constants ----------------
#define BB   8
#define CCH  256
#define HH   64
#define WW   96
#define ND   21
#define NDD  441
#define HW_  6144            // HH*WW

// ---------------- fp16 swizzled images ----------------
// layout: element (row r, k-unit ku) at  r*512 + ((ku ^ (r&7))*16) + (k&7)*2
#define A_IMG 49152          // 96 rows * 512 B
#define B_IMG 69632          // 136 rows * 512 B

__device__ __align__(16) unsigned char g_A[(size_t)BB * HH * A_IMG];  // 25.2 MB
__device__ __align__(16) unsigned char g_B[(size_t)BB * HH * B_IMG];  // 35.7 MB

// ---------------- main-kernel smem (relative to 1024-aligned base) ----------
// A image (49152) + 3-slot B chunk ring (3 * 17408)
#define CHUNK_B   17408      // 136 rows * 128 B (64 K-elems)
#define SM_A      0
#define SM_RING   49152
#define SMEM_REQ  (49152 + 3*CHUNK_B + 1024)   // 102400

// ---------------- ptx helpers (baseline PTX only) -------
__device__ __forceinline__ void cp_async16(uint32_t s, const void* g) {
    asm volatile("cp.async.cg.shared.global [%0], [%1], 16;\n" :: "r"(s), "l"(g));
}
__device__ __forceinline__ void cp_commit() {
    asm volatile("cp.async.commit_group;" ::: "memory");
}
template<int N> __device__ __forceinline__ void cp_wait() {
    asm volatile("cp.async.wait_group %0;" :: "n"(N) : "memory");
}
__device__ __forceinline__ void ldsm4(uint32_t* r, uint32_t a) {
    asm volatile("ldmatrix.sync.aligned.m8n8.x4.shared.b16 {%0,%1,%2,%3}, [%4];"
                 : "=r"(r[0]), "=r"(r[1]), "=r"(r[2]), "=r"(r[3]) : "r"(a));
}
__device__ __forceinline__ void ldsm2(uint32_t* r, uint32_t a) {
    asm volatile("ldmatrix.sync.aligned.m8n8.x2.shared.b16 {%0,%1}, [%2];"
                 : "=r"(r[0]), "=r"(r[1]) : "r"(a));
}
__device__ __forceinline__ void mma16816(float* d, const uint32_t* a, const uint32_t* b) {
    asm volatile("mma.sync.aligned.m16n8k16.row.col.f32.f16.f16.f32 "
                 "{%0,%1,%2,%3}, {%4,%5,%6,%7}, {%8,%9}, {%0,%1,%2,%3};"
                 : "+f"(d[0]), "+f"(d[1]), "+f"(d[2]), "+f"(d[3])
                 : "r"(a[0]), "r"(a[1]), "r"(a[2]), "r"(a[3]), "r"(b[0]), "r"(b[1]));
}

// ================= prepass: one block builds either A or B image for (b,y) ===
__global__ __launch_bounds__(256) void prep_img(const float* __restrict__ in1,
                                                const float* __restrict__ in2) {
    __shared__ float raw[64][97];
    int bid = blockIdx.x;
    bool isB = bid >= (BB * HH);
    int sb = isB ? bid - BB * HH : bid;
    int y = sb & 63, b = sb >> 6;
    int tid = threadIdx.x, w = tid >> 5, lane = tid & 31;
    const float* src_t = isB ? in2 : in1;
    unsigned char* img = isB ? (g_B + (size_t)sb * B_IMG) : (g_A + (size_t)sb * A_IMG);

    for (int q = 0; q < 4; q++) {
        __syncthreads();
        #pragma unroll
        for (int rr = 0; rr < 8; rr++) {
            int c = w * 8 + rr;
            const float* src = src_t + (((size_t)b * CCH + q * 64 + c) * HH + y) * WW;
            #pragma unroll
            for (int m = 0; m < 3; m++)
                raw[c][lane + 32 * m] = src[lane + 32 * m];
        }
        __syncthreads();
        if (!isB) {
            #pragma unroll
            for (int it = 0; it < 3; it++) {
                int u = tid + it * 256;          // u < 768: 96 rows * 8 k-units
                int r = u >> 3, kl = u & 7;
                int ku = q * 8 + kl;
                uint32_t h[4];
                #pragma unroll
                for (int j = 0; j < 4; j++) {
                    __half2 v = __floats2half2_rn(raw[kl * 8 + 2 * j][r],
                                                  raw[kl * 8 + 2 * j + 1][r]);
                    h[j] = *reinterpret_cast<uint32_t*>(&v);
                }
                int off = r * 512 + ((ku ^ (r & 7)) << 4);
                *reinterpret_cast<uint4*>(img + off) = make_uint4(h[0], h[1], h[2], h[3]);
            }
        } else {
            #pragma unroll
            for (int it = 0; it < 5; it++) {
                int u = tid + it * 256;          // u < 1088: 136 rows * 8 k-units
                if (u < 1088) {
                    int r = u >> 3, kl = u & 7;  // r = x' slot 0..135
                    int ku = q * 8 + kl;
                    int xs = r - 20;
                    bool ok = (unsigned)xs < 96u;
                    uint32_t h[4];
                    #pragma unroll
                    for (int j = 0; j < 4; j++) {
                        float lo = ok ? raw[kl * 8 + 2 * j][xs]     : 0.0f;
                        float hi = ok ? raw[kl * 8 + 2 * j + 1][xs] : 0.0f;
                        __half2 v = __floats2half2_rn(lo, hi);
                        h[j] = *reinterpret_cast<uint32_t*>(&v);
                    }
                    int off = r * 512 + ((ku ^ (r & 7)) << 4);
                    *reinterpret_cast<uint4*>(img + off) = make_uint4(h[0], h[1], h[2], h[3]);
                }
            }
        }
    }
}

// ================= main kernel: banded HMMA GEMM per (b,y) ====================
// 12 warps = 6 m-tiles x 2 jj-groups (jn0: jj0-3, jn1: jj4-6). Full K per warp.
// B streamed in 64-K-elem chunks through a 3-slot smem ring -> 2 CTAs/SM.
__global__ __launch_bounds__(384, 2) void corr_hmma(float* __restrict__ out) {
    extern __shared__ __align__(16) unsigned char smraw[];
    uint32_t SB = ((uint32_t)__cvta_generic_to_shared(smraw) + 1023u) & ~1023u;

    int bid = blockIdx.x;
    int y = bid & 63, b = bid >> 6;
    int tid = threadIdx.x, w = tid >> 5, lane = tid & 31;
    int mt = w % 6;          // m16 tile: x in [16mt, 16mt+16)
    int jn = w / 6;          // jj group: 0 -> jj 0..3, 1 -> jj 4..6
    int g = lane >> 2, t = lane & 3;

    // ---- valid dy list ----
    int vlist[ND]; int nv = 0;
    #pragma unroll
    for (int d = 0; d < ND; d++) {
        int y2 = y - 20 + 2 * d;
        if ((unsigned)y2 < (unsigned)HH) vlist[nv++] = d;
    }
    int tot = nv * 4;        // chunk count (4 K-chunks per dy)

    // ---- chunk staging: (vi, q) -> ring slot; verbatim strided copy ----
    auto stage = [&](int ci) {
        int vi = ci >> 2, q = ci & 3;
        int y2 = y - 20 + 2 * vlist[vi];
        const unsigned char* src = g_B + (size_t)(b * HH + y2) * B_IMG + (size_t)(q * 128);
        uint32_t dst = SB + SM_RING + (uint32_t)((ci % 3) * CHUNK_B);
        #pragma unroll
        for (int it = 0; it < 3; it++) {
            int i = tid + it * 384;
            if (i < 1088) {                     // 136 rows * 8 units
                int r = i >> 3, kl = i & 7;
                cp_async16(dst + (uint32_t)(r * 128 + kl * 16),
                           src + (size_t)r * 512 + (size_t)kl * 16);
            }
        }
    };

    // ---- prologue: A image + chunks 0,1 ----
    const unsigned char* imgA = g_A + (size_t)bid * A_IMG;
    #pragma unroll
    for (int it = 0; it < 8; it++) {
        int i = tid + it * 384;                 // i < 3072
        cp_async16(SB + SM_A + (uint32_t)(i * 16), imgA + (size_t)i * 16);
    }
    stage(0); cp_commit();                      // G0 = A + chunk0
    stage(1); cp_commit();                      // G1 = chunk1

    // ---- zero invalid-dy output slices (overlaps prologue cp.async) ----
    #pragma unroll 1
    for (int d = 0; d < ND; d++) {
        int y2 = y - 20 + 2 * d;
        if ((unsigned)y2 >= (unsigned)HH) {
            for (int i = tid; i < ND * WW; i += 384) {
                int dj = i / WW, x = i - dj * WW;
                out[(((size_t)b * NDD + d * ND + dj) * HH + y) * WW + x] = 0.0f;
            }
        }
    }

    // ---- per-lane ldmatrix address precompute ----
    uint32_t arow  = 16u * mt + (lane & 7) + 8u * ((lane >> 3) & 1);
    uint32_t abase = SB + SM_A + arow * 512u;
    uint32_t ar7   = arow & 7u;
    uint32_t akoff = (uint32_t)(lane >> 4);     // +0 / +1 k-unit
    uint32_t bkoff = (uint32_t)((lane >> 3) & 1);

    // B row addresses (chunk-local: row stride 128B, swizzle by row&7)
    int pbase = jn ? 4 : 0;
    uint32_t br0 = 8u * (2u * mt + (uint32_t)pbase + (uint32_t)(lane >> 4)) + (lane & 7);
    uint32_t br1 = jn ? (8u * (2u * mt + 6u) + (lane & 7))
                      : (8u * (2u * mt + 2u + (uint32_t)(lane >> 4)) + (lane & 7));
    uint32_t br0o = br0 * 128u, br0x = br0 & 7u;
    uint32_t br1o = br1 * 128u, br1x = br1 & 7u;

    const float scale = 1.0f / 256.0f;

    float acc[4][4];
    #pragma unroll
    for (int jj = 0; jj < 4; jj++)
        #pragma unroll
        for (int r = 0; r < 4; r++) acc[jj][r] = 0.0f;

    // ---- main chunk loop ----
    #pragma unroll 1
    for (int ci = 0; ci < tot; ci++) {
        cp_wait<1>();                 // chunk ci resident (G(ci) done)
        __syncthreads();              // all warps finished chunk ci-1 -> slot free
        if (ci + 2 < tot) stage(ci + 2);
        cp_commit();

        int q = ci & 3;
        uint32_t slot = SB + SM_RING + (uint32_t)((ci % 3) * CHUNK_B);

        #pragma unroll
        for (int ks = 0; ks < 4; ks++) {
            uint32_t aku = (uint32_t)(q * 8 + 2 * ks) + akoff;
            uint32_t a[4];
            ldsm4(a, abase + ((aku ^ ar7) << 4));

            uint32_t kl = (uint32_t)(2 * ks) + bkoff;   // chunk-local k-unit
            if (jn == 0) {
                uint32_t bfr[4][2];
                ldsm4(&bfr[0][0], slot + br0o + ((kl ^ br0x) << 4));
                ldsm4(&bfr[2][0], slot + br1o + ((kl ^ br1x) << 4));
                #pragma unroll
                for (int jj = 0; jj < 4; jj++)
                    mma16816(acc[jj], a, bfr[jj]);
            } else {
                uint32_t bfr[3][2];
                ldsm4(&bfr[0][0], slot + br0o + ((kl ^ br0x) << 4));
                ldsm2(&bfr[2][0], slot + br1o + ((kl ^ br1x) << 4));
                #pragma unroll
                for (int jj = 0; jj < 3; jj++)
                    mma16816(acc[jj], a, bfr[jj]);
            }
        }

        // ---- epilogue at end of each dy (q==3): band extraction, no reduce ----
        if (q == 3) {
            int dyi = vlist[ci >> 2];
            size_t obase = (((size_t)b * NDD + dyi * ND) * HH + y) * WW;
            int njj = jn ? 3 : 4;
            #pragma unroll
            for (int jl = 0; jl < 4; jl++) {
                if (jl < njj) {
                    int jj = pbase + jl;
                    #pragma unroll
                    for (int rh = 0; rh < 2; rh++) {
                        int di = 4 * jj - 4 * rh + t - (g >> 1);
                        float v = (g & 1) ? acc[jl][2 * rh + 1] : acc[jl][2 * rh];
                        int x = 16 * mt + g + 8 * rh;
                        if ((unsigned)di <= 20u)
                            out[obase + (size_t)di * HW_ + x] = v * scale;
                    }
                    #pragma unroll
                    for (int r = 0; r < 4; r++) acc[jl][r] = 0.0f;
                }
            }
        }
    }
}

// ================= launch =================
extern "C" void kernel_launch(void* const* d_in, const int* in_sizes, int n_in,
                              void* d_out, int out_size)
{
    const float* in1 = (const float*)d_in[0];
    const float* in2 = (const float*)d_in[1];
    float* out = (float*)d_out;

    cudaFuncSetAttribute(corr_hmma, cudaFuncAttributeMaxDynamicSharedMemorySize, SMEM_REQ);

    prep_img<<<2 * BB * HH, 256>>>(in1, in2);
    corr_hmma<<<BB * HH, 384, SMEM_REQ>>>(out);
}

// round 9
// speedup vs baseline: 1.2931x; 1.2931x over previous
#include <cuda_runtime.h>
#include <cuda_fp16.h>
#include <cstdint>

// ---------------- problem constants ----------------
#define BB   8
#define CCH  256
#define HH   64
#define WW   96
#define ND   21
#define NDD  441
#define HW_  6144            // HH*WW

// ---------------- fp16 swizzled images ----------------
// element (row r, k-unit ku) at  r*512 + ((ku ^ (r&7))*16) + (k&7)*2
#define A_IMG 49152          // 96 rows * 512 B
#define B_IMG 69632          // 136 rows * 512 B (rows 0..19,116..135 never written/read)

__device__ __align__(16) unsigned char g_A[(size_t)BB * HH * A_IMG];
__device__ __align__(16) unsigned char g_B[(size_t)BB * HH * B_IMG];

// ---------------- main-kernel smem (relative to 1024-aligned base) ----------
// A image 49152 (overlaid by reduce scratch after A-hoist) + 2 B buffers
#define SM_A    0
#define SM_RED  0            // 6 slots * 7168 = 43008 <= 49152
#define SM_B0   49152
#define SM_B1   118784
#define SMEM_REQ (188416 + 1024)

// ---------------- ptx helpers (baseline PTX only) -------
__device__ __forceinline__ void cp_async16(uint32_t s, const void* g) {
    asm volatile("cp.async.cg.shared.global [%0], [%1], 16;\n" :: "r"(s), "l"(g));
}
__device__ __forceinline__ void cp_commit() {
    asm volatile("cp.async.commit_group;" ::: "memory");
}
template<int N> __device__ __forceinline__ void cp_wait() {
    asm volatile("cp.async.wait_group %0;" :: "n"(N) : "memory");
}
__device__ __forceinline__ void bar_sync(int id, int cnt) {
    asm volatile("bar.sync %0, %1;" :: "r"(id), "r"(cnt) : "memory");
}
__device__ __forceinline__ void ldsm4(uint32_t* r, uint32_t a) {
    asm volatile("ldmatrix.sync.aligned.m8n8.x4.shared.b16 {%0,%1,%2,%3}, [%4];"
                 : "=r"(r[0]), "=r"(r[1]), "=r"(r[2]), "=r"(r[3]) : "r"(a));
}
__device__ __forceinline__ void ldsm2(uint32_t* r, uint32_t a) {
    asm volatile("ldmatrix.sync.aligned.m8n8.x2.shared.b16 {%0,%1}, [%2];"
                 : "=r"(r[0]), "=r"(r[1]) : "r"(a));
}
__device__ __forceinline__ void mma16816(float* d, const uint32_t* a, const uint32_t* b) {
    asm volatile("mma.sync.aligned.m16n8k16.row.col.f32.f16.f16.f32 "
                 "{%0,%1,%2,%3}, {%4,%5,%6,%7}, {%8,%9}, {%0,%1,%2,%3};"
                 : "+f"(d[0]), "+f"(d[1]), "+f"(d[2]), "+f"(d[3])
                 : "r"(a[0]), "r"(a[1]), "r"(a[2]), "r"(a[3]), "r"(b[0]), "r"(b[1]));
}

// ================= prepass: one block builds either A or B image for (b,y) ===
__global__ __launch_bounds__(256) void prep_img(const float* __restrict__ in1,
                                                const float* __restrict__ in2) {
    __shared__ float raw[64][97];
    int bid = blockIdx.x;
    bool isB = bid >= (BB * HH);
    int sb = isB ? bid - BB * HH : bid;
    int y = sb & 63, b = sb >> 6;
    int tid = threadIdx.x, w = tid >> 5, lane = tid & 31;
    const float* src_t = isB ? in2 : in1;
    unsigned char* img = isB ? (g_B + (size_t)sb * B_IMG) : (g_A + (size_t)sb * A_IMG);

    for (int q = 0; q < 4; q++) {
        __syncthreads();
        #pragma unroll
        for (int rr = 0; rr < 8; rr++) {
            int c = w * 8 + rr;
            const float* src = src_t + (((size_t)b * CCH + q * 64 + c) * HH + y) * WW;
            #pragma unroll
            for (int m = 0; m < 3; m++)
                raw[c][lane + 32 * m] = src[lane + 32 * m];
        }
        __syncthreads();
        if (!isB) {
            #pragma unroll
            for (int it = 0; it < 3; it++) {
                int u = tid + it * 256;          // u < 768: 96 rows * 8 k-units
                int r = u >> 3, kl = u & 7;
                int ku = q * 8 + kl;
                uint32_t h[4];
                #pragma unroll
                for (int j = 0; j < 4; j++) {
                    __half2 v = __floats2half2_rn(raw[kl * 8 + 2 * j][r],
                                                  raw[kl * 8 + 2 * j + 1][r]);
                    h[j] = *reinterpret_cast<uint32_t*>(&v);
                }
                int off = r * 512 + ((ku ^ (r & 7)) << 4);
                *reinterpret_cast<uint4*>(img + off) = make_uint4(h[0], h[1], h[2], h[3]);
            }
        } else {
            // only data rows 20..115 (x' in range); pad rows never read from image
            #pragma unroll
            for (int it = 0; it < 3; it++) {
                int u = tid + it * 256;          // u < 768
                int r = 20 + (u >> 3), kl = u & 7;
                int ku = q * 8 + kl;
                int xs = r - 20;                 // 0..95 always valid
                uint32_t h[4];
                #pragma unroll
                for (int j = 0; j < 4; j++) {
                    __half2 v = __floats2half2_rn(raw[kl * 8 + 2 * j][xs],
                                                  raw[kl * 8 + 2 * j + 1][xs]);
                    h[j] = *reinterpret_cast<uint32_t*>(&v);
                }
                int off = r * 512 + ((ku ^ (r & 7)) << 4);
                *reinterpret_cast<uint4*>(img + off) = make_uint4(h[0], h[1], h[2], h[3]);
            }
        }
    }
}

// ================= main kernel ================================================
// 12 warps = 2 pipeline groups x (3 m-pairs x 2 k-halves).
// Group g computes dy rows vi ≡ g (mod 2) out of its own B buffer; named-barrier
// sync only. A fragments hoisted to registers; A smem overlaid by reduce scratch.
__global__ __launch_bounds__(384, 1) void corr_hmma(float* __restrict__ out) {
    extern __shared__ __align__(16) unsigned char smraw[];
    uint32_t SB = ((uint32_t)__cvta_generic_to_shared(smraw) + 1023u) & ~1023u;

    int bid = blockIdx.x;
    int y = bid & 63, b = bid >> 6;
    int tid = threadIdx.x, w = tid >> 5, lane = tid & 31;
    int g  = w / 6;          // pipeline group
    int wl = w - g * 6;
    int pr = wl % 3;         // m-pair: m16 tiles 2pr, 2pr+1
    int kh = wl / 3;         // k-half: k-units kh*16 .. kh*16+15
    int t192 = tid - g * 192;
    int lg = lane >> 2, t = lane & 3;
    int l7 = lane & 7;

    // ---- valid dy list ----
    int vlist[ND]; int nv = 0;
    #pragma unroll
    for (int d = 0; d < ND; d++) {
        int y2 = y - 20 + 2 * d;
        if ((unsigned)y2 < (unsigned)HH) vlist[nv++] = d;
    }

    // ---- staging: copy data rows 20..115 (full 512B rows) into buffer vi&1 ----
    auto stage = [&](int vi) {
        int y2 = y - 20 + 2 * vlist[vi];
        const unsigned char* src = g_B + (size_t)(b * HH + y2) * B_IMG;
        uint32_t dst = SB + ((vi & 1) ? SM_B1 : SM_B0);
        #pragma unroll
        for (int it = 0; it < 16; it++) {
            int i = t192 + it * 192;             // i < 3072 = 96 rows * 32 units
            int off = (20 + (i >> 5)) * 512 + (i & 31) * 16;
            cp_async16(dst + off, src + off);
        }
    };

    // ---- prologue: A image (G0), then this group's first B row (G1) ----
    const unsigned char* imgA = g_A + (size_t)bid * A_IMG;
    #pragma unroll
    for (int it = 0; it < 8; it++) {
        int i = tid + it * 384;                  // i < 3072
        cp_async16(SB + SM_A + (uint32_t)(i * 16), imgA + (size_t)i * 16);
    }
    cp_commit();
    stage(g);
    cp_commit();

    // ---- zero pad rows (0..19, 116..135) of both buffers ----
    for (int i = tid; i < 2560; i += 384) {
        int bu = i / 1280, j = i - bu * 1280;
        int rr = j >> 5, unit = j & 31;
        int r = (rr < 20) ? rr : rr + 96;        // 0..19 and 116..135
        uint32_t ad = SB + (bu ? SM_B1 : SM_B0) + (uint32_t)(r * 512 + unit * 16);
        asm volatile("st.shared.v4.b32 [%0], {%1,%1,%1,%1};" :: "r"(ad), "r"(0) : "memory");
    }

    // ---- zero invalid-dy output slices ----
    #pragma unroll 1
    for (int d = 0; d < ND; d++) {
        int y2 = y - 20 + 2 * d;
        if ((unsigned)y2 >= (unsigned)HH) {
            for (int i = tid; i < ND * WW; i += 384) {
                int dj = i / WW, x = i - dj * WW;
                out[(((size_t)b * NDD + d * ND + dj) * HH + y) * WW + x] = 0.0f;
            }
        }
    }

    // ---- A resident -> hoist fragments to registers ----
    cp_wait<1>();             // G0 (A) complete; G1 (first B) may still be in flight
    __syncthreads();

    uint32_t a[2][8][4];
    #pragma unroll
    for (int m = 0; m < 2; m++) {
        uint32_t arow = 16u * (2 * pr + m) + (uint32_t)l7 + 8u * ((lane >> 3) & 1);
        uint32_t abase = SB + SM_A + arow * 512u;
        #pragma unroll
        for (int ks = 0; ks < 8; ks++) {
            uint32_t aku = (uint32_t)(kh * 16 + 2 * ks) + (uint32_t)(lane >> 4);
            ldsm4(a[m][ks], abase + ((aku ^ (uint32_t)l7) << 4));
        }
    }
    __syncthreads();          // all hoists done -> A region becomes reduce scratch

    // ---- B ldsm row offsets (all rows ≡ l7 mod 8 -> shared swizzle term) ----
    uint32_t rowoff4[4];
    #pragma unroll
    for (int q = 0; q < 4; q++)
        rowoff4[q] = (8u * (uint32_t)(4 * pr + 2 * q + (lane >> 4)) + (uint32_t)l7) * 512u;
    uint32_t rowoff8 = (8u * (uint32_t)(4 * pr + 8) + (uint32_t)l7) * 512u;
    uint32_t kadd = (uint32_t)((lane >> 3) & 1);

    uint32_t redslot = SB + SM_RED + (uint32_t)((g * 3 + pr) * 7168);
    const float scale = 1.0f / 256.0f;

    float acc[2][7][4];
    #pragma unroll
    for (int m = 0; m < 2; m++)
        #pragma unroll
        for (int jj = 0; jj < 7; jj++)
            #pragma unroll
            for (int r = 0; r < 4; r++) acc[m][jj][r] = 0.0f;

    // ---- group pipeline over this group's dy rows ----
    #pragma unroll 1
    for (int vi = g; vi < nv; vi += 2) {
        cp_wait<0>();                        // B(vi) landed
        bar_sync(g + 1, 192);                // group-wide visibility + buffer free
        uint32_t SBB = SB + ((vi & 1) ? SM_B1 : SM_B0);

        #pragma unroll
        for (int ks = 0; ks < 8; ks++) {
            uint32_t sw = (((uint32_t)(kh * 16 + 2 * ks) + kadd) ^ (uint32_t)l7) << 4;
            uint32_t bfr[9][2];
            ldsm4(&bfr[0][0], SBB + rowoff4[0] + sw);
            ldsm4(&bfr[2][0], SBB + rowoff4[1] + sw);
            ldsm4(&bfr[4][0], SBB + rowoff4[2] + sw);
            ldsm4(&bfr[6][0], SBB + rowoff4[3] + sw);
            ldsm2(&bfr[8][0], SBB + rowoff8 + sw);

            #pragma unroll
            for (int m = 0; m < 2; m++)
                #pragma unroll
                for (int jj = 0; jj < 7; jj++)
                    mma16816(acc[m][jj], a[m][ks], bfr[2 * m + jj]);
        }

        // ---- split-K reduce (scratch overlays old A region) ----
        if (kh == 0) {
            #pragma unroll
            for (int m = 0; m < 2; m++)
                #pragma unroll
                for (int jj = 0; jj < 7; jj++)
                    #pragma unroll
                    for (int r = 0; r < 4; r++) {
                        asm volatile("st.shared.f32 [%0], %1;"
                            :: "r"(redslot + (uint32_t)(((m * 28 + jj * 4 + r) * 32 + lane) * 4)),
                               "f"(acc[m][jj][r]) : "memory");
                        acc[m][jj][r] = 0.0f;
                    }
        }
        bar_sync(g + 1, 192);
        if (kh == 1) {
            int dyi = vlist[vi];
            size_t obase = (((size_t)b * NDD + dyi * ND) * HH + y) * WW;
            #pragma unroll
            for (int m = 0; m < 2; m++) {
                int mt = 2 * pr + m;
                #pragma unroll
                for (int jj = 0; jj < 7; jj++) {
                    #pragma unroll
                    for (int r = 0; r < 4; r++) {
                        float p;
                        asm volatile("ld.shared.f32 %0, [%1];"
                            : "=f"(p)
                            : "r"(redslot + (uint32_t)(((m * 28 + jj * 4 + r) * 32 + lane) * 4)));
                        acc[m][jj][r] += p;
                    }
                    #pragma unroll
                    for (int rh = 0; rh < 2; rh++) {
                        int di = 4 * jj - 4 * rh + t - (lg >> 1);
                        float v = (lg & 1) ? acc[m][jj][2 * rh + 1] : acc[m][jj][2 * rh];
                        int x = 16 * mt + lg + 8 * rh;
                        if ((unsigned)di <= 20u)
                            out[obase + (size_t)di * HW_ + x] = v * scale;
                    }
                    #pragma unroll
                    for (int r = 0; r < 4; r++) acc[m][jj][r] = 0.0f;
                }
            }
        }

        // ---- stage next row of this group (overlaps other group's compute) ----
        if (vi + 2 < nv) { stage(vi + 2); cp_commit(); }
    }
}

// ================= launch =================
extern "C" void kernel_launch(void* const* d_in, const int* in_sizes, int n_in,
                              void* d_out, int out_size)
{
    const float* in1 = (const float*)d_in[0];
    const float* in2 = (const float*)d_in[1];
    float* out = (float*)d_out;

    cudaFuncSetAttribute(corr_hmma, cudaFuncAttributeMaxDynamicSharedMemorySize, SMEM_REQ);

    prep_img<<<2 * BB * HH, 256>>>(in1, in2);
    corr_hmma<<<BB * HH, 384, SMEM_REQ>>>(out);
}